// round 2
// baseline (speedup 1.0000x reference)
#include <cuda_runtime.h>

// Problem constants (fixed by the reference setup)
#define NUM_TOKENS   32768
#define NUM_BLOCKS   1024
#define BLOCK_SIZE   128
#define NUM_KV_HEADS 8
#define HEAD_DIM     128

#define NUM_SLOTS    (NUM_BLOCKS * BLOCK_SIZE)          // 131072
#define SLOT_FLOATS  (NUM_KV_HEADS * HEAD_DIM)          // 1024 floats = 4KB per slot
#define TOTAL_F4     (NUM_SLOTS * SLOT_FLOATS / 4)      // 33,554,432 float4

#define FP8_MAX 240.0f

// slot -> token map (512 KB). __device__ global: allocation-free scratch.
__device__ int g_slot_map[NUM_SLOTS];

__global__ void init_map_kernel() {
    int i = blockIdx.x * blockDim.x + threadIdx.x;
    if (i < NUM_SLOTS) g_slot_map[i] = -1;
}

__global__ void fill_map_kernel(const int* __restrict__ block_indices,
                                const int* __restrict__ block_offset) {
    int t = blockIdx.x * blockDim.x + threadIdx.x;
    if (t < NUM_TOKENS) {
        int slot = block_indices[t] * BLOCK_SIZE + block_offset[t];
        g_slot_map[slot] = t;   // slots are unique per token (permutation) -> no race
    }
}

__global__ void __launch_bounds__(256)
fused_scatter_dequant_kernel(const float4* __restrict__ input,   // [NUM_TOKENS * 256] float4
                             const float4* __restrict__ cache,   // [TOTAL_F4]
                             const float*  __restrict__ p_scale_in,
                             const float*  __restrict__ p_scale_out,
                             float4* __restrict__ out) {
    int i = blockIdx.x * blockDim.x + threadIdx.x;   // float4 index
    // 256 float4 per slot; warp (32 lanes) never crosses a slot boundary
    int slot = i >> 8;
    int tok  = g_slot_map[slot];                      // broadcast read, L2-resident
    float so = *p_scale_out;

    float4 v;
    if (tok >= 0) {
        float si = *p_scale_in;
        v = input[tok * 256 + (i & 255)];
        v.x = fminf(fmaxf(v.x / si, -FP8_MAX), FP8_MAX) * so;
        v.y = fminf(fmaxf(v.y / si, -FP8_MAX), FP8_MAX) * so;
        v.z = fminf(fmaxf(v.z / si, -FP8_MAX), FP8_MAX) * so;
        v.w = fminf(fmaxf(v.w / si, -FP8_MAX), FP8_MAX) * so;
    } else {
        v = cache[i];
        v.x *= so; v.y *= so; v.z *= so; v.w *= so;
    }
    out[i] = v;
}

extern "C" void kernel_launch(void* const* d_in, const int* in_sizes, int n_in,
                              void* d_out, int out_size) {
    const float* input         = (const float*)d_in[0];
    const float* cache         = (const float*)d_in[1];
    const int*   block_indices = (const int*)d_in[2];
    const int*   block_offset  = (const int*)d_in[3];
    const float* scale_input   = (const float*)d_in[4];
    const float* scale_output  = (const float*)d_in[5];
    float* out = (float*)d_out;

    init_map_kernel<<<(NUM_SLOTS + 255) / 256, 256>>>();
    fill_map_kernel<<<(NUM_TOKENS + 255) / 256, 256>>>(block_indices, block_offset);
    fused_scatter_dequant_kernel<<<TOTAL_F4 / 256, 256>>>(
        (const float4*)input, (const float4*)cache,
        scale_input, scale_output, (float4*)out);
}

// round 5
// speedup vs baseline: 1.2402x; 1.2402x over previous
#include <cuda_runtime.h>

// Problem constants (fixed by the reference setup)
#define NUM_TOKENS   32768
#define NUM_BLOCKS   1024
#define BLOCK_SIZE   128
#define NUM_KV_HEADS 8
#define HEAD_DIM     128

#define NUM_SLOTS    (NUM_BLOCKS * BLOCK_SIZE)          // 131072
#define SLOT_F4      (NUM_KV_HEADS * HEAD_DIM / 4)      // 256 float4 per slot (4KB)
#define TOTAL_F4     (NUM_SLOTS * SLOT_F4)              // 33,554,432 float4

#define FP8_MAX 240.0f

// slot -> token map (512 KB) + precomputed scale constants.
// __device__ globals: allocation-free scratch.
__device__ int   g_slot_map[NUM_SLOTS];
__device__ float g_c;    // scale_output / scale_input
__device__ float g_so;   // scale_output
__device__ float g_lo;   // min(-FP8_MAX*so, FP8_MAX*so)
__device__ float g_hi;   // max(-FP8_MAX*so, FP8_MAX*so)

__global__ void init_map_kernel() {
    int i = blockIdx.x * blockDim.x + threadIdx.x;
    ((int4*)g_slot_map)[i] = make_int4(-1, -1, -1, -1);
}

__global__ void fill_map_kernel(const int* __restrict__ block_indices,
                                const int* __restrict__ block_offset,
                                const float* __restrict__ p_si,
                                const float* __restrict__ p_so) {
    int t = blockIdx.x * blockDim.x + threadIdx.x;
    if (t < NUM_TOKENS) {
        int slot = block_indices[t] * BLOCK_SIZE + block_offset[t];
        g_slot_map[slot] = t;   // slots unique per token -> no race
    }
    if (t == 0) {
        float si = *p_si, so = *p_so;
        g_so = so;
        g_c  = so / si;
        float a = -FP8_MAX * so, b = FP8_MAX * so;
        g_lo = fminf(a, b);
        g_hi = fmaxf(a, b);
    }
}

// One block = 4 consecutive slots (1024 float4). Each thread handles one
// float4 per slot (warp-stride coalesced), 4 total -> MLP=4, amortized
// indexing, single uniform int4 map load per block.
__global__ void __launch_bounds__(256)
fused_scatter_dequant_kernel(const float4* __restrict__ input,   // [NUM_TOKENS * 256]
                             const float4* __restrict__ cache,   // [TOTAL_F4]
                             float4* __restrict__ out) {
    const int t = threadIdx.x;
    const int b = blockIdx.x;
    const int base = b * (4 * SLOT_F4);          // < 2^31, int ok

    const float c  = g_c;
    const float so = g_so;
    const float lo = g_lo;
    const float hi = g_hi;

    const int4 tok4 = ((const int4*)g_slot_map)[b];   // uniform LDG.128
    int tok[4] = {tok4.x, tok4.y, tok4.z, tok4.w};

    float4 v[4];
#pragma unroll
    for (int k = 0; k < 4; k++) {
        const float4* src = (tok[k] >= 0)
            ? (input + tok[k] * SLOT_F4 + t)
            : (cache + base + k * SLOT_F4 + t);
        v[k] = __ldcs(src);
    }

#pragma unroll
    for (int k = 0; k < 4; k++) {
        float4 r;
        if (tok[k] >= 0) {
            r.x = fminf(fmaxf(v[k].x * c, lo), hi);
            r.y = fminf(fmaxf(v[k].y * c, lo), hi);
            r.z = fminf(fmaxf(v[k].z * c, lo), hi);
            r.w = fminf(fmaxf(v[k].w * c, lo), hi);
        } else {
            r.x = v[k].x * so;
            r.y = v[k].y * so;
            r.z = v[k].z * so;
            r.w = v[k].w * so;
        }
        __stcs(out + base + k * SLOT_F4 + t, r);
    }
}

extern "C" void kernel_launch(void* const* d_in, const int* in_sizes, int n_in,
                              void* d_out, int out_size) {
    const float* input         = (const float*)d_in[0];
    const float* cache         = (const float*)d_in[1];
    const int*   block_indices = (const int*)d_in[2];
    const int*   block_offset  = (const int*)d_in[3];
    const float* scale_input   = (const float*)d_in[4];
    const float* scale_output  = (const float*)d_in[5];
    float* out = (float*)d_out;

    init_map_kernel<<<NUM_SLOTS / 4 / 256, 256>>>();
    fill_map_kernel<<<(NUM_TOKENS + 255) / 256, 256>>>(block_indices, block_offset,
                                                       scale_input, scale_output);
    fused_scatter_dequant_kernel<<<NUM_SLOTS / 4, 256>>>(
        (const float4*)input, (const float4*)cache, (float4*)out);
}

// round 10
// speedup vs baseline: 1.2429x; 1.0022x over previous
#include <cuda_runtime.h>

// Problem constants (fixed by the reference setup)
#define NUM_TOKENS   32768
#define NUM_BLOCKS   1024
#define BLOCK_SIZE   128
#define NUM_KV_HEADS 8
#define HEAD_DIM     128

#define NUM_SLOTS    (NUM_BLOCKS * BLOCK_SIZE)          // 131072
#define SLOT_F4      (NUM_KV_HEADS * HEAD_DIM / 4)      // 256 float4 per slot (4KB)

#define FP8_MAX 240.0f

// Self-validating slot -> token map (512 KB) + precomputed scale constants.
// No init needed: an entry 'tok' is trusted only if block_indices[tok]*128 +
// block_offset[tok] == slot. .bss zeros / stale replay values either fail the
// check (-> cache path) or are the correct token anyway (same inputs per
// replay). Map only ever holds values in [0, NUM_TOKENS).
__device__ int   g_slot_map[NUM_SLOTS];
__device__ float g_c;    // scale_output / scale_input
__device__ float g_so;   // scale_output
__device__ float g_lo;   // min(-FP8_MAX*so, FP8_MAX*so)
__device__ float g_hi;   // max(-FP8_MAX*so, FP8_MAX*so)

__global__ void fill_map_kernel(const int* __restrict__ block_indices,
                                const int* __restrict__ block_offset,
                                const float* __restrict__ p_si,
                                const float* __restrict__ p_so) {
    int t = blockIdx.x * blockDim.x + threadIdx.x;
    if (t < NUM_TOKENS) {
        int slot = block_indices[t] * BLOCK_SIZE + block_offset[t];
        g_slot_map[slot] = t;   // slots unique per token -> no race
    }
    if (t == 0) {
        float si = *p_si, so = *p_so;
        g_so = so;
        g_c  = so / si;
        float a = -FP8_MAX * so, b = FP8_MAX * so;
        g_lo = fminf(a, b);
        g_hi = fmaxf(a, b);
    }
}

// One block = 4 consecutive slots (1024 float4). Each thread handles one
// float4 per slot (warp-stride coalesced), 4 total -> MLP=4, amortized
// indexing, single uniform int4 map load per block + self-validation.
__global__ void __launch_bounds__(256)
fused_scatter_dequant_kernel(const float4* __restrict__ input,   // [NUM_TOKENS * 256]
                             const float4* __restrict__ cache,
                             const int*    __restrict__ block_indices,
                             const int*    __restrict__ block_offset,
                             float4* __restrict__ out) {
    const int t = threadIdx.x;
    const int b = blockIdx.x;
    const int base = b * (4 * SLOT_F4);          // < 2^31, int ok

    const float c  = g_c;
    const float so = g_so;
    const float lo = g_lo;
    const float hi = g_hi;

    const int4 tok4 = ((const int4*)g_slot_map)[b];   // uniform LDG.128
    int tok[4] = {tok4.x, tok4.y, tok4.z, tok4.w};

    bool is_tok[4];
#pragma unroll
    for (int k = 0; k < 4; k++) {
        // validate: does this token actually map back to this slot?
        int slot = b * 4 + k;
        is_tok[k] = (block_indices[tok[k]] * BLOCK_SIZE + block_offset[tok[k]] == slot);
    }

    float4 v[4];
#pragma unroll
    for (int k = 0; k < 4; k++) {
        const float4* src = is_tok[k]
            ? (input + tok[k] * SLOT_F4 + t)
            : (cache + base + k * SLOT_F4 + t);
        v[k] = __ldcs(src);
    }

#pragma unroll
    for (int k = 0; k < 4; k++) {
        float4 r;
        if (is_tok[k]) {
            r.x = fminf(fmaxf(v[k].x * c, lo), hi);
            r.y = fminf(fmaxf(v[k].y * c, lo), hi);
            r.z = fminf(fmaxf(v[k].z * c, lo), hi);
            r.w = fminf(fmaxf(v[k].w * c, lo), hi);
        } else {
            r.x = v[k].x * so;
            r.y = v[k].y * so;
            r.z = v[k].z * so;
            r.w = v[k].w * so;
        }
        __stcs(out + base + k * SLOT_F4 + t, r);
    }
}

extern "C" void kernel_launch(void* const* d_in, const int* in_sizes, int n_in,
                              void* d_out, int out_size) {
    const float* input         = (const float*)d_in[0];
    const float* cache         = (const float*)d_in[1];
    const int*   block_indices = (const int*)d_in[2];
    const int*   block_offset  = (const int*)d_in[3];
    const float* scale_input   = (const float*)d_in[4];
    const float* scale_output  = (const float*)d_in[5];
    float* out = (float*)d_out;

    fill_map_kernel<<<(NUM_TOKENS + 255) / 256, 256>>>(block_indices, block_offset,
                                                       scale_input, scale_output);
    fused_scatter_dequant_kernel<<<NUM_SLOTS / 4, 256>>>(
        (const float4*)input, (const float4*)cache,
        block_indices, block_offset, (float4*)out);
}